// round 5
// baseline (speedup 1.0000x reference)
#include <cuda_runtime.h>
#include <math.h>
#include <stdint.h>

// ---------------- problem constants ----------------
#define TWO_B 512
#define BHALF 256
#define DDIM  512
#define NCLS  100000
#define SCALE 30.0f
#define S_LOG2E 43.280851226668914f  // 30 * log2(e)
#define COS_M 0.8775825618903728f
#define SIN_M 0.4794255386042030f
#define TH   (-0.8775825618903728f)
#define MMRG  0.2397127693021015f

// ---------------- GEMM tiling ----------------
#define MT      128                   // rows per CTA
#define NT      256                   // classes per CTA
#define NTILES  391                   // ceil(NCLS/NT)
#define NPART   392
#define KC      64                    // K int8 elems per chunk (64 B/row)
#define NCHUNK  8
#define NSTAGE  4
#define ROWB    80                    // padded bytes per smem row

// smem layout (bytes)
#define A_OFF   0
#define A_STG   (MT * ROWB)                    // 10240
#define B_OFF   (NSTAGE * A_STG)               // 40960
#define B_STG   (NT * ROWB)                    // 20480
#define SW_OFF  (B_OFF + NSTAGE * B_STG)       // 122880 : sw[256] floats
#define SR_OFF  (SW_OFF + NT * 4)              // 123904 : sRowP[4][128]
#define SMEM_BYTES (SR_OFF + 4 * MT * 4)       // 125952

// ---------------- device scratch ----------------
__device__ __align__(16) int8_t g_e8[TWO_B * DDIM];
__device__ __align__(16) int8_t g_w8[(size_t)NCLS * DDIM];
__device__ float g_escale[TWO_B];
__device__ float g_wscale[NCLS];
__device__ float g_part[TWO_B * NPART];
__device__ float g_coslab[TWO_B];
__device__ float g_nll[TWO_B];

// ---------------- helpers ----------------
__device__ __forceinline__ uint32_t smem_u32(const void* p) {
    uint32_t a;
    asm("{ .reg .u64 t; cvta.to.shared.u64 t, %1; cvt.u32.u64 %0, t; }" : "=r"(a) : "l"(p));
    return a;
}
__device__ __forceinline__ void cp16(uint32_t dst, const void* src) {
    asm volatile("cp.async.cg.shared.global [%0], [%1], 16;" :: "r"(dst), "l"(src));
}
__device__ __forceinline__ void cp_commit() { asm volatile("cp.async.commit_group;"); }
__device__ __forceinline__ void cp_wait2()  { asm volatile("cp.async.wait_group 2;"); }

__device__ __forceinline__ void ldm_x4(uint32_t* r, uint32_t addr) {
    asm volatile("ldmatrix.sync.aligned.m8n8.x4.shared.b16 {%0,%1,%2,%3}, [%4];"
                 : "=r"(r[0]), "=r"(r[1]), "=r"(r[2]), "=r"(r[3]) : "r"(addr));
}
__device__ __forceinline__ void mma_s8(int* d, const uint32_t* a, const uint32_t* b) {
    asm volatile(
        "mma.sync.aligned.m16n8k32.row.col.s32.s8.s8.s32 "
        "{%0,%1,%2,%3}, {%4,%5,%6,%7}, {%8,%9}, {%0,%1,%2,%3};"
        : "+r"(d[0]), "+r"(d[1]), "+r"(d[2]), "+r"(d[3])
        : "r"(a[0]), "r"(a[1]), "r"(a[2]), "r"(a[3]), "r"(b[0]), "r"(b[1]));
}
__device__ __forceinline__ uint32_t pack4(int q0, int q1, int q2, int q3) {
    return (uint32_t)(q0 & 0xFF) | ((uint32_t)(q1 & 0xFF) << 8) |
           ((uint32_t)(q2 & 0xFF) << 16) | ((uint32_t)(q3 & 0xFF) << 24);
}
__device__ __forceinline__ int q8(float v, float qs) {
    int q = __float2int_rn(v * qs);
    return max(-127, min(127, q));
}

// ============================================================
// Kernel A: normalize embeddings -> int8 + per-row scale
// ============================================================
__global__ void k_norm_emb(const float* __restrict__ img,
                           const float* __restrict__ prof) {
    int n = blockIdx.x;
    const float* src = (n < BHALF) ? (img + (size_t)n * DDIM)
                                   : (prof + (size_t)(n - BHALF) * DDIM);
    __shared__ float wsum[8], wmax[8];
    __shared__ float s_qs, s_sc;
    float ss = 0.f, mx = 0.f;
    float v0 = src[threadIdx.x], v1 = src[threadIdx.x + 256];
    ss = v0 * v0 + v1 * v1;
    mx = fmaxf(fabsf(v0), fabsf(v1));
    #pragma unroll
    for (int o = 16; o; o >>= 1) {
        ss += __shfl_xor_sync(0xffffffffu, ss, o);
        mx = fmaxf(mx, __shfl_xor_sync(0xffffffffu, mx, o));
    }
    if ((threadIdx.x & 31) == 0) { wsum[threadIdx.x >> 5] = ss; wmax[threadIdx.x >> 5] = mx; }
    __syncthreads();
    if (threadIdx.x == 0) {
        float t = 0.f, m = 0.f;
        #pragma unroll
        for (int w = 0; w < 8; w++) { t += wsum[w]; m = fmaxf(m, wmax[w]); }
        float rinv = rsqrtf(t);
        s_qs = 127.f / m;                  // quant mult on raw v (rinv cancels)
        s_sc = m * rinv / 127.f;           // dequant scale on normalized
        g_escale[n] = s_sc;
    }
    __syncthreads();
    float qs = s_qs;
    // each thread quantizes 2 elements -> uchar2
    uchar2 o0, o1;
    o0.x = (unsigned char)(q8(src[threadIdx.x * 2], qs) & 0xFF);
    o0.y = (unsigned char)(q8(src[threadIdx.x * 2 + 1], qs) & 0xFF);
    ((uchar2*)g_e8)[(size_t)n * 256 + threadIdx.x] = o0;
    (void)o1;
}

// ============================================================
// Kernel W: normalize weight rows -> int8 + scale (warp/row)
// ============================================================
__global__ void __launch_bounds__(256)
k_wprep(const float* __restrict__ weight) {
    int row = blockIdx.x * 8 + (threadIdx.x >> 5);
    int lane = threadIdx.x & 31;
    if (row >= NCLS) return;
    const float4* src = (const float4*)(weight + (size_t)row * DDIM);
    float4 v[4];
    float ss = 0.f, mx = 0.f;
    #pragma unroll
    for (int t = 0; t < 4; t++) {
        v[t] = src[lane * 4 + t];
        ss = fmaf(v[t].x, v[t].x, fmaf(v[t].y, v[t].y,
             fmaf(v[t].z, v[t].z, fmaf(v[t].w, v[t].w, ss))));
        mx = fmaxf(mx, fmaxf(fmaxf(fabsf(v[t].x), fabsf(v[t].y)),
                             fmaxf(fabsf(v[t].z), fabsf(v[t].w))));
    }
    #pragma unroll
    for (int o = 16; o; o >>= 1) {
        ss += __shfl_xor_sync(0xffffffffu, ss, o);
        mx = fmaxf(mx, __shfl_xor_sync(0xffffffffu, mx, o));
    }
    float rinv = rsqrtf(ss);
    float qs = 127.f / mx;
    if (lane == 0) g_wscale[row] = mx * rinv / 127.f;
    uint4 out;
    out.x = pack4(q8(v[0].x, qs), q8(v[0].y, qs), q8(v[0].z, qs), q8(v[0].w, qs));
    out.y = pack4(q8(v[1].x, qs), q8(v[1].y, qs), q8(v[1].z, qs), q8(v[1].w, qs));
    out.z = pack4(q8(v[2].x, qs), q8(v[2].y, qs), q8(v[2].z, qs), q8(v[2].w, qs));
    out.w = pack4(q8(v[3].x, qs), q8(v[3].y, qs), q8(v[3].z, qs), q8(v[3].w, qs));
    ((uint4*)(g_w8 + (size_t)row * DDIM))[lane] = out;
}

// ============================================================
// Kernel B: int8 IMMA GEMM + exp epilogue
//   CTA 128 rows x 256 classes, 512 threads (warps 4M x 4N).
// ============================================================
__global__ void __launch_bounds__(512, 1)
k_main(const long long* __restrict__ label) {
    extern __shared__ char smem[];
    const uint32_t sb = smem_u32(smem);
    const int tid   = threadIdx.x;
    const int lane  = tid & 31;
    const int wrp   = tid >> 5;
    const int warpM = wrp & 3;
    const int warpN = wrp >> 2;
    const int g     = lane >> 2;
    const int tig   = lane & 3;

    const int m0   = blockIdx.x * MT;
    const int col0 = blockIdx.y * NT;

    int acc[2][8][4];
    #pragma unroll
    for (int mt = 0; mt < 2; mt++)
        #pragma unroll
        for (int nt = 0; nt < 8; nt++)
            #pragma unroll
            for (int e = 0; e < 4; e++) acc[mt][nt][e] = 0;

    // ldmatrix per-lane offsets (within stage)
    // A x4: m0=(r0-7,b0-15) m1=(r8-15,b0-15) m2=(r0-7,b16-31) m3=(r8-15,b16-31)
    const uint32_t a_lo = (uint32_t)((warpM * 32 + (lane & 7) + ((lane >> 3) & 1) * 8) * ROWB
                                     + (lane >> 4) * 16);
    // B x4: m0=(c0-7,b0-15) m1=(c0-7,b16-31) m2=(c8-15,b0-15) m3=(c8-15,b16-31)
    const uint32_t b_lo = (uint32_t)((warpN * 64 + (lane & 7) + ((lane >> 4) & 1) * 8) * ROWB
                                     + ((lane >> 3) & 1) * 16);

    // ---- chunk loader: rows of 64B = 4 cp16 ----
    auto load_chunk = [&](int c, int st) {
        {   // A: 128 rows x 4 = 512 cp16
            int r = tid >> 2, j = tid & 3;
            uint32_t dst = sb + A_OFF + (uint32_t)st * A_STG + (uint32_t)(r * ROWB + j * 16);
            cp16(dst, g_e8 + (size_t)(m0 + r) * DDIM + c * KC + j * 16);
        }
        #pragma unroll
        for (int i = 0; i < 2; i++) {   // B: 256 rows x 4 = 1024 cp16
            int idx = i * 512 + tid;
            int r = idx >> 2, j = idx & 3;
            int crow = col0 + r; if (crow >= NCLS) crow = NCLS - 1;
            uint32_t dst = sb + B_OFF + (uint32_t)st * B_STG + (uint32_t)(r * ROWB + j * 16);
            cp16(dst, g_w8 + (size_t)crow * DDIM + c * KC + j * 16);
        }
    };

    load_chunk(0, 0); cp_commit();
    load_chunk(1, 1); cp_commit();
    load_chunk(2, 2); cp_commit();

    // stage sw (class dequant scales) into smem
    if (tid < NT) {
        int crow = col0 + tid; if (crow >= NCLS) crow = NCLS - 1;
        ((float*)(smem + SW_OFF))[tid] = g_wscale[crow];
    }

    for (int c = 0; c < NCHUNK; c++) {
        const int st = c & 3;
        cp_wait2();
        __syncthreads();
        if (c + 3 < NCHUNK) load_chunk(c + 3, (c + 3) & 3);
        cp_commit();

        const uint32_t aB = sb + A_OFF + (uint32_t)st * A_STG + a_lo;
        const uint32_t bB = sb + B_OFF + (uint32_t)st * B_STG + b_lo;

        #pragma unroll
        for (int ks = 0; ks < 2; ks++) {     // 2 x K=32
            uint32_t aF[2][4];
            ldm_x4(aF[0], aB + ks * 32);
            ldm_x4(aF[1], aB + ks * 32 + 16 * ROWB);
            uint32_t bF[4][4];               // 4 quads x 16 classes
            #pragma unroll
            for (int nq = 0; nq < 4; nq++)
                ldm_x4(bF[nq], bB + ks * 32 + (uint32_t)nq * 16 * ROWB);
            #pragma unroll
            for (int mt = 0; mt < 2; mt++)
                #pragma unroll
                for (int nt = 0; nt < 8; nt++)
                    mma_s8(acc[mt][nt], aF[mt], &bF[nt >> 1][(nt & 1) * 2]);
        }
    }
    __syncthreads();

    // ---- epilogue ----
    const float* s_sw = (const float*)(smem + SW_OFF);
    float* sRowP = (float*)(smem + SR_OFF);

    #pragma unroll
    for (int mt = 0; mt < 2; mt++) {
        const int lrow0 = warpM * 32 + mt * 16 + g;
        const int grow0 = m0 + lrow0;
        const int grow1 = grow0 + 8;
        const float se0 = g_escale[grow0], se1 = g_escale[grow1];
        const float k0 = se0 * S_LOG2E, k1 = se1 * S_LOG2E;
        const int lab0 = (int)label[grow0 & 255];
        const int lab1 = (int)label[grow1 & 255];
        float sum0 = 0.f, sum1 = 0.f;
        #pragma unroll
        for (int nt = 0; nt < 8; nt++) {
            #pragma unroll
            for (int e = 0; e < 2; e++) {
                const int cl = warpN * 64 + (nt >> 1) * 16 + (nt & 1) * 8 + tig * 2 + e;
                const int cc = col0 + cl;
                const float sw = s_sw[cl];
                const float t0 = (float)acc[mt][nt][e]     * sw;
                const float t1 = (float)acc[mt][nt][2 + e] * sw;
                if (cc < NCLS) {
                    sum0 += exp2f(t0 * k0);
                    sum1 += exp2f(t1 * k1);
                    if (cc == lab0) g_coslab[grow0] = t0 * se0;
                    if (cc == lab1) g_coslab[grow1] = t1 * se1;
                }
            }
        }
        sum0 += __shfl_xor_sync(0xffffffffu, sum0, 1);
        sum0 += __shfl_xor_sync(0xffffffffu, sum0, 2);
        sum1 += __shfl_xor_sync(0xffffffffu, sum1, 1);
        sum1 += __shfl_xor_sync(0xffffffffu, sum1, 2);
        if (tig == 0) {
            sRowP[warpN * MT + lrow0]     = sum0;
            sRowP[warpN * MT + lrow0 + 8] = sum1;
        }
    }
    __syncthreads();
    if (tid < MT) {
        float s = sRowP[tid] + sRowP[MT + tid] + sRowP[2 * MT + tid] + sRowP[3 * MT + tid];
        g_part[(size_t)(m0 + tid) * NPART + blockIdx.y] = s;
    }
}

// ============================================================
// Kernel C1: per-row reduce + margin
// ============================================================
__global__ void k_final1(void) {
    int n = blockIdx.x;
    float s = 0.f;
    for (int t = threadIdx.x; t < NTILES; t += 128)
        s += g_part[(size_t)n * NPART + t];
    __shared__ float wsum[4];
    #pragma unroll
    for (int o = 16; o; o >>= 1) s += __shfl_xor_sync(0xffffffffu, s, o);
    if ((threadIdx.x & 31) == 0) wsum[threadIdx.x >> 5] = s;
    __syncthreads();
    if (threadIdx.x == 0) {
        float tot = wsum[0] + wsum[1] + wsum[2] + wsum[3];
        float cosl = g_coslab[n];
        float sine = sqrtf(fminf(fmaxf(1.f - cosl * cosl, 0.f), 1.f));
        float phi = cosl * COS_M - sine * SIN_M;
        if (!(cosl > TH)) phi = cosl - MMRG;
        float total = tot - exp2f(cosl * S_LOG2E) + exp2f(phi * S_LOG2E);
        g_nll[n] = logf(total) - SCALE * phi;
    }
}

// ============================================================
// Kernel C2: mean
// ============================================================
__global__ void k_final2(float* __restrict__ out) {
    int n = threadIdx.x;
    float v = g_nll[n];
    __shared__ float wsum[16];
    #pragma unroll
    for (int o = 16; o; o >>= 1) v += __shfl_xor_sync(0xffffffffu, v, o);
    if ((n & 31) == 0) wsum[n >> 5] = v;
    __syncthreads();
    if (n == 0) {
        float t = 0.f;
        #pragma unroll
        for (int w = 0; w < 16; w++) t += wsum[w];
        out[0] = t / (float)TWO_B;
    }
}

// ============================================================
// launch
// ============================================================
extern "C" void kernel_launch(void* const* d_in, const int* in_sizes, int n_in,
                              void* d_out, int out_size) {
    const float*     img  = (const float*)d_in[0];
    const float*     prof = (const float*)d_in[1];
    const float*     w    = (const float*)d_in[2];
    const long long* lab  = (const long long*)d_in[3];
    float* out = (float*)d_out;

    cudaFuncSetAttribute(k_main, cudaFuncAttributeMaxDynamicSharedMemorySize, SMEM_BYTES);

    k_norm_emb<<<TWO_B, 256>>>(img, prof);
    k_wprep<<<(NCLS + 7) / 8, 256>>>(w);
    dim3 grid(4, NTILES);
    k_main<<<grid, 512, SMEM_BYTES>>>(lab);
    k_final1<<<TWO_B, 128>>>();
    k_final2<<<1, TWO_B>>>(out);
}

// round 6
// speedup vs baseline: 2.0281x; 2.0281x over previous
#include <cuda_runtime.h>
#include <math.h>
#include <stdint.h>

// ---------------- problem constants ----------------
#define TWO_B 512
#define BHALF 256
#define DDIM  512
#define NCLS  100000
#define SCALE 30.0f
#define S_LOG2E 43.280851226668914f  // 30 * log2(e)
#define COS_M 0.8775825618903728f
#define SIN_M 0.4794255386042030f
#define TH   (-0.8775825618903728f)
#define MMRG  0.2397127693021015f

// ---------------- GEMM tiling ----------------
#define MT      128                   // rows per CTA
#define NT      128                   // classes per CTA
#define NTILES  782                   // ceil(NCLS/NT)
#define NPART   784
#define KC      32                    // K bf16 elems per chunk (64 B/row)
#define NCHUNK  16
#define NSTAGE  4
#define ROWB    80                    // padded bytes per smem row (conflict-free)

// smem layout (bytes)
#define A_OFF   0
#define A_STG   (MT * ROWB)                    // 10240
#define B_OFF   (NSTAGE * A_STG)               // 40960
#define B_STG   (NT * ROWB)                    // 10240
#define SR_OFF  (B_OFF + NSTAGE * B_STG)       // 81920 : sRowP[4][128] floats
#define SMEM_BYTES (SR_OFF + 4 * MT * 4)       // 83968

// ---------------- device scratch ----------------
__device__ __align__(16) uint16_t g_embn[TWO_B * DDIM];      // normalized emb, bf16
__device__ __align__(16) uint16_t g_wn[(size_t)NCLS * DDIM]; // normalized weight, bf16
__device__ float g_part[TWO_B * NPART];
__device__ float g_coslab[TWO_B];
__device__ float g_nll[TWO_B];

// ---------------- helpers ----------------
__device__ __forceinline__ uint32_t smem_u32(const void* p) {
    uint32_t a;
    asm("{ .reg .u64 t; cvta.to.shared.u64 t, %1; cvt.u32.u64 %0, t; }" : "=r"(a) : "l"(p));
    return a;
}
__device__ __forceinline__ void cp16(uint32_t dst, const void* src) {
    asm volatile("cp.async.cg.shared.global [%0], [%1], 16;" :: "r"(dst), "l"(src));
}
__device__ __forceinline__ void cp_commit() { asm volatile("cp.async.commit_group;"); }
__device__ __forceinline__ void cp_wait2()  { asm volatile("cp.async.wait_group 2;"); }

__device__ __forceinline__ uint32_t pack_bf16x2(float lo, float hi) {
    uint32_t r;
    asm("cvt.rn.bf16x2.f32 %0, %1, %2;" : "=r"(r) : "f"(hi), "f"(lo));
    return r;
}
__device__ __forceinline__ void ldm_x4(uint32_t* r, uint32_t addr) {
    asm volatile("ldmatrix.sync.aligned.m8n8.x4.shared.b16 {%0,%1,%2,%3}, [%4];"
                 : "=r"(r[0]), "=r"(r[1]), "=r"(r[2]), "=r"(r[3]) : "r"(addr));
}
__device__ __forceinline__ void mma_bf16(float* d, const uint32_t* a, const uint32_t* b) {
    asm volatile(
        "mma.sync.aligned.m16n8k16.row.col.f32.bf16.bf16.f32 "
        "{%0,%1,%2,%3}, {%4,%5,%6,%7}, {%8,%9}, {%0,%1,%2,%3};"
        : "+f"(d[0]), "+f"(d[1]), "+f"(d[2]), "+f"(d[3])
        : "r"(a[0]), "r"(a[1]), "r"(a[2]), "r"(a[3]), "r"(b[0]), "r"(b[1]));
}

// ============================================================
// Kernel A: normalize embeddings -> bf16
// ============================================================
__global__ void k_norm_emb(const float* __restrict__ img,
                           const float* __restrict__ prof) {
    int n = blockIdx.x;
    const float* src = (n < BHALF) ? (img + (size_t)n * DDIM)
                                   : (prof + (size_t)(n - BHALF) * DDIM);
    __shared__ float wsum[8];
    __shared__ float srinv;
    float ss = 0.f;
    for (int d = threadIdx.x; d < DDIM; d += blockDim.x) {
        float v = src[d];
        ss += v * v;
    }
    #pragma unroll
    for (int o = 16; o; o >>= 1) ss += __shfl_xor_sync(0xffffffffu, ss, o);
    if ((threadIdx.x & 31) == 0) wsum[threadIdx.x >> 5] = ss;
    __syncthreads();
    if (threadIdx.x == 0) {
        float t = 0.f;
        #pragma unroll
        for (int w = 0; w < 8; w++) t += wsum[w];
        srinv = rsqrtf(t);
    }
    __syncthreads();
    float rinv = srinv;
    for (int p = threadIdx.x; p < DDIM / 2; p += blockDim.x) {
        float a = src[p * 2] * rinv, b = src[p * 2 + 1] * rinv;
        ((uint32_t*)g_embn)[(size_t)n * (DDIM / 2) + p] = pack_bf16x2(a, b);
    }
}

// ============================================================
// Kernel W: normalize weight rows -> bf16 (one warp per class)
// ============================================================
__global__ void __launch_bounds__(256)
k_wprep(const float* __restrict__ weight) {
    int row = blockIdx.x * 8 + (threadIdx.x >> 5);
    int lane = threadIdx.x & 31;
    if (row >= NCLS) return;
    const float4* src = (const float4*)(weight + (size_t)row * DDIM);
    float4 v[4];
    float ss = 0.f;
    #pragma unroll
    for (int t = 0; t < 4; t++) {
        v[t] = src[lane * 4 + t];
        ss = fmaf(v[t].x, v[t].x, fmaf(v[t].y, v[t].y,
             fmaf(v[t].z, v[t].z, fmaf(v[t].w, v[t].w, ss))));
    }
    #pragma unroll
    for (int o = 16; o; o >>= 1) ss += __shfl_xor_sync(0xffffffffu, ss, o);
    float rinv = rsqrtf(ss);
    uint4 out[2];
    uint32_t* ou = (uint32_t*)out;
    #pragma unroll
    for (int t = 0; t < 4; t++) {
        ou[t * 2 + 0] = pack_bf16x2(v[t].x * rinv, v[t].y * rinv);
        ou[t * 2 + 1] = pack_bf16x2(v[t].z * rinv, v[t].w * rinv);
    }
    uint4* dst = (uint4*)(g_wn + (size_t)row * DDIM);
    dst[lane * 2 + 0] = out[0];
    dst[lane * 2 + 1] = out[1];
}

// ============================================================
// Kernel B: bf16 mma.sync GEMM + exp epilogue
//   CTA 128 rows x 128 classes, 256 threads (warps 2M x 4N),
//   2 CTAs/SM to fill pipeline bubbles.
// ============================================================
__global__ void __launch_bounds__(256, 2)
k_main(const long long* __restrict__ label) {
    extern __shared__ char smem[];
    const uint32_t sb = smem_u32(smem);
    const int tid   = threadIdx.x;
    const int lane  = tid & 31;
    const int wrp   = tid >> 5;
    const int warpM = wrp & 1;     // 0..1 (64 rows each)
    const int warpN = wrp >> 1;    // 0..3 (32 cols each)
    const int g     = lane >> 2;
    const int tig   = lane & 3;

    const int m0   = blockIdx.x * MT;
    const int col0 = blockIdx.y * NT;

    float acc[4][4][4];
    #pragma unroll
    for (int mt = 0; mt < 4; mt++)
        #pragma unroll
        for (int nt = 0; nt < 4; nt++)
            #pragma unroll
            for (int e = 0; e < 4; e++) acc[mt][nt][e] = 0.f;

    // per-lane ldmatrix offsets (bytes, within a stage)
    const uint32_t a_lo = (uint32_t)((warpM * 64 + (lane & 15)) * ROWB + (lane >> 4) * 16);
    const uint32_t b_lo = (uint32_t)((warpN * 32 + (lane & 7) + ((lane >> 4) << 3)) * ROWB
                                     + (((lane >> 3) & 1) << 4));

    // ---- chunk loader (bf16 rows: 64B = 4 x cp16), 256 threads ----
    auto load_chunk = [&](int c, int st) {
        #pragma unroll
        for (int i = 0; i < 2; i++) {   // A: 128 rows x 4 = 512 cp16
            int idx = i * 256 + tid;
            int r = idx >> 2, j = idx & 3;
            uint32_t dst = sb + A_OFF + (uint32_t)st * A_STG + (uint32_t)(r * ROWB + j * 16);
            cp16(dst, g_embn + (size_t)(m0 + r) * DDIM + c * KC + j * 8);
        }
        #pragma unroll
        for (int i = 0; i < 2; i++) {   // B: 128 rows x 4 = 512 cp16
            int idx = i * 256 + tid;
            int r = idx >> 2, j = idx & 3;
            int crow = col0 + r; if (crow >= NCLS) crow = NCLS - 1;
            uint32_t dst = sb + B_OFF + (uint32_t)st * B_STG + (uint32_t)(r * ROWB + j * 16);
            cp16(dst, g_wn + (size_t)crow * DDIM + c * KC + j * 8);
        }
    };

    load_chunk(0, 0); cp_commit();
    load_chunk(1, 1); cp_commit();
    load_chunk(2, 2); cp_commit();

    for (int c = 0; c < NCHUNK; c++) {
        const int st = c & 3;
        cp_wait2();
        __syncthreads();
        if (c + 3 < NCHUNK) load_chunk(c + 3, (c + 3) & 3);
        cp_commit();

        const uint32_t aB = sb + A_OFF + (uint32_t)st * A_STG + a_lo;
        const uint32_t bB = sb + B_OFF + (uint32_t)st * B_STG + b_lo;

        #pragma unroll
        for (int ks = 0; ks < 2; ks++) {
            uint32_t aF[4][4];
            #pragma unroll
            for (int mt = 0; mt < 4; mt++)
                ldm_x4(aF[mt], aB + ks * 32 + (uint32_t)mt * 16 * ROWB);
            uint32_t bF[2][4];
            #pragma unroll
            for (int p = 0; p < 2; p++)
                ldm_x4(bF[p], bB + ks * 32 + (uint32_t)p * 16 * ROWB);
            #pragma unroll
            for (int mt = 0; mt < 4; mt++)
                #pragma unroll
                for (int nt = 0; nt < 4; nt++)
                    mma_bf16(acc[mt][nt], aF[mt], &bF[nt >> 1][(nt & 1) * 2]);
        }
    }
    __syncthreads();

    // ---- epilogue: exp row-sums + label gather ----
    float* sRowP = (float*)(smem + SR_OFF);

    #pragma unroll
    for (int mt = 0; mt < 4; mt++) {
        const int lrow0 = warpM * 64 + mt * 16 + g;
        const int grow0 = m0 + lrow0;
        const int grow1 = grow0 + 8;
        const int lab0 = (int)label[grow0 & 255];
        const int lab1 = (int)label[grow1 & 255];
        float sum0 = 0.f, sum1 = 0.f;
        #pragma unroll
        for (int nt = 0; nt < 4; nt++) {
            #pragma unroll
            for (int e = 0; e < 2; e++) {
                const int cc = col0 + warpN * 32 + nt * 8 + tig * 2 + e;
                const float c0 = acc[mt][nt][e];
                const float c1 = acc[mt][nt][2 + e];
                if (cc < NCLS) {
                    sum0 += exp2f(c0 * S_LOG2E);
                    sum1 += exp2f(c1 * S_LOG2E);
                    if (cc == lab0) g_coslab[grow0] = c0;
                    if (cc == lab1) g_coslab[grow1] = c1;
                }
            }
        }
        sum0 += __shfl_xor_sync(0xffffffffu, sum0, 1);
        sum0 += __shfl_xor_sync(0xffffffffu, sum0, 2);
        sum1 += __shfl_xor_sync(0xffffffffu, sum1, 1);
        sum1 += __shfl_xor_sync(0xffffffffu, sum1, 2);
        if (tig == 0) {
            sRowP[warpN * MT + lrow0]     = sum0;
            sRowP[warpN * MT + lrow0 + 8] = sum1;
        }
    }
    __syncthreads();
    if (tid < MT) {
        float s = sRowP[tid] + sRowP[MT + tid] + sRowP[2 * MT + tid] + sRowP[3 * MT + tid];
        g_part[(size_t)(m0 + tid) * NPART + blockIdx.y] = s;
    }
}

// ============================================================
// Kernel C1: per-row reduce + margin
// ============================================================
__global__ void k_final1(void) {
    int n = blockIdx.x;
    float s = 0.f;
    for (int t = threadIdx.x; t < NTILES; t += 128)
        s += g_part[(size_t)n * NPART + t];
    __shared__ float wsum[4];
    #pragma unroll
    for (int o = 16; o; o >>= 1) s += __shfl_xor_sync(0xffffffffu, s, o);
    if ((threadIdx.x & 31) == 0) wsum[threadIdx.x >> 5] = s;
    __syncthreads();
    if (threadIdx.x == 0) {
        float tot = wsum[0] + wsum[1] + wsum[2] + wsum[3];
        float cosl = g_coslab[n];
        float sine = sqrtf(fminf(fmaxf(1.f - cosl * cosl, 0.f), 1.f));
        float phi = cosl * COS_M - sine * SIN_M;
        if (!(cosl > TH)) phi = cosl - MMRG;
        float total = tot - exp2f(cosl * S_LOG2E) + exp2f(phi * S_LOG2E);
        g_nll[n] = logf(total) - SCALE * phi;
    }
}

// ============================================================
// Kernel C2: mean
// ============================================================
__global__ void k_final2(float* __restrict__ out) {
    int n = threadIdx.x;
    float v = g_nll[n];
    __shared__ float wsum[16];
    #pragma unroll
    for (int o = 16; o; o >>= 1) v += __shfl_xor_sync(0xffffffffu, v, o);
    if ((n & 31) == 0) wsum[n >> 5] = v;
    __syncthreads();
    if (n == 0) {
        float t = 0.f;
        #pragma unroll
        for (int w = 0; w < 16; w++) t += wsum[w];
        out[0] = t / (float)TWO_B;
    }
}

// ============================================================
// launch
// ============================================================
extern "C" void kernel_launch(void* const* d_in, const int* in_sizes, int n_in,
                              void* d_out, int out_size) {
    const float*     img  = (const float*)d_in[0];
    const float*     prof = (const float*)d_in[1];
    const float*     w    = (const float*)d_in[2];
    const long long* lab  = (const long long*)d_in[3];
    float* out = (float*)d_out;

    cudaFuncSetAttribute(k_main, cudaFuncAttributeMaxDynamicSharedMemorySize, SMEM_BYTES);

    k_norm_emb<<<TWO_B, 256>>>(img, prof);
    k_wprep<<<(NCLS + 7) / 8, 256>>>(w);
    dim3 grid(4, NTILES);                 // M fastest -> weight L2 reuse
    k_main<<<grid, 256, SMEM_BYTES>>>(lab);
    k_final1<<<TWO_B, 128>>>();
    k_final2<<<1, TWO_B>>>(out);
}